// round 8
// baseline (speedup 1.0000x reference)
#include <cuda_runtime.h>
#include <math.h>

#define Bq 16
#define Sq 2048
#define Dq 128
#define Hq 8
#define BH 128
#define MCH 16                 // mem chunk (timesteps)
#define SCH 64                 // scan chunk
#define NCH (Sq/SCH)
#define CUT 1e-7f

// dynamic smem float layout
#define OFF_WK 0
#define OFF_WV 16384
#define OFF_X  32768           // 16 rows * stride 132 = 2112
#define OFF_K  34880           // 16 * 132 = 2112
#define OFF_V  36992           // 16 * 132 = 2112
#define OFF_C  39104           // 2048
#define SMEM_FLOATS 41152

// ---------------------------------------------------------------------------
// One block per (b,h).
// Phase 1: backward scan w/ early exit. f_t = sigmoid(x_t.Wf_h + bf_h) via
//          direct coalesced LDG + 8-lane shfl reduce; chunk suffix products
//          via warp-0 shfl scan; c_t = w_t*sp_t in smem; stop when sp < CUT.
// Phase 2: chunked (16-step) K/V projection + rank-16 outer products into a
//          4x8 register tile; final acc += P*M0 (skipped when P==0); store.
// ---------------------------------------------------------------------------
__global__ __launch_bounds__(512) void fused_kernel(
    const float* __restrict__ x, const float* __restrict__ M0,
    const float* __restrict__ router, const int* __restrict__ memid,
    const float* __restrict__ Wk, const float* __restrict__ bk,
    const float* __restrict__ Wv, const float* __restrict__ bv,
    const float* __restrict__ Wf, const float* __restrict__ bf,
    float* __restrict__ out, int nm)
{
    extern __shared__ float sm[];
    float* Wk_s = sm + OFF_WK;
    float* Wv_s = sm + OFF_WV;
    float* x_s  = sm + OFF_X;     // [row][d], stride 132
    float* k_s  = sm + OFF_K;     // [row][d], stride 132 (rows c-scaled)
    float* v_s  = sm + OFF_V;
    float* c_s  = sm + OFF_C;     // indexed by global t

    __shared__ float wfh[Dq];
    __shared__ float f_s[SCH], csp[SCH];
    __shared__ float s_sp, s_newsp;
    __shared__ int   s_t0i;

    int tid = threadIdx.x, bh = blockIdx.x, b = bh >> 3, h = bh & 7;

    // head weights into smem
    for (int idx = tid; idx < Dq * 32; idx += 512) {
        int d = idx >> 5, q = idx & 31;
        *(float4*)&Wk_s[d * Dq + q * 4] =
            *(const float4*)&Wk[(size_t)d * (Dq * Hq) + h * Dq + q * 4];
        *(float4*)&Wv_s[d * Dq + q * 4] =
            *(const float4*)&Wv[(size_t)d * (Dq * Hq) + h * Dq + q * 4];
    }
    for (int d = tid; d < Dq; d += 512) wfh[d] = Wf[d * Hq + h];
    float bfh = bf[h];
    int mid = *memid;
    if (tid == 0) { s_sp = 1.0f; s_t0i = SCH; }
    __syncthreads();

    // ---- phase 1: backward scan with early exit ----
    int t0_exact = 0;
    float P = 0.0f;

    for (int ci = NCH - 1; ci >= 0; ci--) {
        int tc = ci * SCH;

        // f for 64 timesteps: 8 threads per t, direct LDG + shfl reduce
        {
            int t8 = tid >> 3, sub = tid & 7;
            const float* xp = &x[((size_t)b * Sq + tc + t8) * Dq + sub * 16];
            float a = 0.f;
            #pragma unroll
            for (int j = 0; j < 4; j++) {
                float4 xv = *(const float4*)&xp[j * 4];
                const float* wp = &wfh[sub * 16 + j * 4];
                a += xv.x * wp[0] + xv.y * wp[1] + xv.z * wp[2] + xv.w * wp[3];
            }
            a += __shfl_xor_sync(0xffffffffu, a, 1);
            a += __shfl_xor_sync(0xffffffffu, a, 2);
            a += __shfl_xor_sync(0xffffffffu, a, 4);
            if (sub == 0) f_s[t8] = 1.0f / (1.0f + __expf(-(a + bfh)));
        }
        __syncthreads();

        // warp 0: suffix-product scan over the 64 f values (2 per lane)
        if (tid < 32) {
            float f0 = f_s[2 * tid], f1 = f_s[2 * tid + 1];
            float p = f0 * f1;
            float incl = p;                       // prod_{j>=lane} p_j
            #pragma unroll
            for (int off = 1; off < 32; off <<= 1) {
                float v = __shfl_down_sync(0xffffffffu, incl, off);
                if (tid + off < 32) incl *= v;
            }
            float excl = __shfl_down_sync(0xffffffffu, incl, 1);
            if (tid == 31) excl = 1.0f;           // prod_{j>lane} p_j
            float sp0 = s_sp;
            float c1 = sp0 * excl;                // suffix after t = 2*lane+1
            float c0 = c1 * f1;                   // suffix after t = 2*lane
            csp[2 * tid]     = c0;
            csp[2 * tid + 1] = c1;
            if (tid == 0) s_newsp = sp0 * incl;   // suffix incl. whole chunk
        }
        __syncthreads();

        if (tid < SCH) {
            float w = router[((size_t)b * Sq + tc + tid) * nm + mid];
            c_s[tc + tid] = w * csp[tid];
            if (csp[tid] >= CUT) atomicMin(&s_t0i, tid);
        }
        __syncthreads();

        float nsp = s_newsp;
        if (nsp < CUT) { t0_exact = tc + s_t0i; break; }   // uniform decision
        if (tid == 0) { s_sp = nsp; s_t0i = SCH; }
        if (ci == 0) { P = nsp; t0_exact = 0; }
        __syncthreads();
    }
    __syncthreads();

    // ---- phase 2: chunked projection + outer products ----
    int dg = tid >> 4, eg = tid & 15, d0 = dg * 4, e0 = eg * 8;
    float acc[4][8];
    #pragma unroll
    for (int r = 0; r < 4; r++)
        #pragma unroll
        for (int j = 0; j < 8; j++) acc[r][j] = 0.f;

    int half = tid >> 8, id2 = tid & 255;
    int rg = id2 & 15;        // projection row (timestep within chunk)
    int cg = id2 >> 4;        // projection cols cg*8..+7
    float* op = half ? v_s : k_s;
    const float* Ws = half ? Wv_s : Wk_s;
    float bias[8];
    {
        const float* bsrc = half ? bv : bk;
        #pragma unroll
        for (int j = 0; j < 8; j++) bias[j] = bsrc[h * Dq + cg * 8 + j];
    }

    int t_start = t0_exact & ~(MCH - 1);
    for (int tc = t_start; tc < Sq; tc += MCH) {
        __syncthreads();
        // stage x chunk row-major: x_s[row][d], one warp per row
        {
            int row = tid >> 5, lane = tid & 31;
            float4 xv = *(const float4*)&x[((size_t)b * Sq + tc + row) * Dq + lane * 4];
            *(float4*)&x_s[row * 132 + lane * 4] = xv;
        }
        __syncthreads();

        // projection: 1 row x 8 cols of the 16x128 K-or-V chunk
        float pa[8];
        #pragma unroll
        for (int j = 0; j < 8; j++) pa[j] = 0.f;

        #pragma unroll 4
        for (int d4 = 0; d4 < Dq / 4; d4++) {
            float4 xa = *(const float4*)&x_s[rg * 132 + d4 * 4];
            float xr[4] = {xa.x, xa.y, xa.z, xa.w};
            #pragma unroll
            for (int u = 0; u < 4; u++) {
                int d = d4 * 4 + u;
                float4 w0 = *(const float4*)&Ws[d * Dq + cg * 8];
                float4 w1 = *(const float4*)&Ws[d * Dq + cg * 8 + 4];
                pa[0] += xr[u] * w0.x; pa[1] += xr[u] * w0.y;
                pa[2] += xr[u] * w0.z; pa[3] += xr[u] * w0.w;
                pa[4] += xr[u] * w1.x; pa[5] += xr[u] * w1.y;
                pa[6] += xr[u] * w1.z; pa[7] += xr[u] * w1.w;
            }
        }
        {
            float scale = half ? 1.0f : c_s[tc + rg];   // fold c_t into k rows
            float o[8];
            #pragma unroll
            for (int j = 0; j < 8; j++) o[j] = (pa[j] + bias[j]) * scale;
            *(float4*)&op[rg * 132 + cg * 8]     = make_float4(o[0], o[1], o[2], o[3]);
            *(float4*)&op[rg * 132 + cg * 8 + 4] = make_float4(o[4], o[5], o[6], o[7]);
        }
        __syncthreads();

        // rank-16 outer-product update of the 4x8 tile
        #pragma unroll 4
        for (int i = 0; i < MCH; i++) {
            float4 k0 = *(const float4*)&k_s[i * 132 + d0];
            float4 v0 = *(const float4*)&v_s[i * 132 + e0];
            float4 v1 = *(const float4*)&v_s[i * 132 + e0 + 4];
            float kk[4] = {k0.x, k0.y, k0.z, k0.w};
            float vv[8] = {v0.x, v0.y, v0.z, v0.w, v1.x, v1.y, v1.z, v1.w};
            #pragma unroll
            for (int r = 0; r < 4; r++)
                #pragma unroll
                for (int q = 0; q < 8; q++)
                    acc[r][q] += kk[r] * vv[q];
        }
    }

    // add P*M0 only if the full scan completed (P != 0); else contribution < CUT
    if (P != 0.0f) {
        #pragma unroll
        for (int r = 0; r < 4; r++) {
            float4 m0 = *(const float4*)&M0[(((size_t)bh * Dq) + d0 + r) * Dq + e0];
            float4 m1 = *(const float4*)&M0[(((size_t)bh * Dq) + d0 + r) * Dq + e0 + 4];
            acc[r][0] += P * m0.x; acc[r][1] += P * m0.y;
            acc[r][2] += P * m0.z; acc[r][3] += P * m0.w;
            acc[r][4] += P * m1.x; acc[r][5] += P * m1.y;
            acc[r][6] += P * m1.z; acc[r][7] += P * m1.w;
        }
    }

    #pragma unroll
    for (int r = 0; r < 4; r++) {
        *(float4*)&out[(((size_t)bh * Dq) + d0 + r) * Dq + e0] =
            make_float4(acc[r][0], acc[r][1], acc[r][2], acc[r][3]);
        *(float4*)&out[(((size_t)bh * Dq) + d0 + r) * Dq + e0 + 4] =
            make_float4(acc[r][4], acc[r][5], acc[r][6], acc[r][7]);
    }
}

// ---------------------------------------------------------------------------
extern "C" void kernel_launch(void* const* d_in, const int* in_sizes, int n_in,
                              void* d_out, int out_size)
{
    const float* x      = (const float*)d_in[0];
    const float* M      = (const float*)d_in[1];
    const float* router = (const float*)d_in[2];
    const int*   memid  = (const int*)d_in[3];
    const float* Wk     = (const float*)d_in[4];
    const float* bk     = (const float*)d_in[5];
    const float* Wv     = (const float*)d_in[6];
    const float* bv     = (const float*)d_in[7];
    const float* Wf     = (const float*)d_in[8];
    const float* bf     = (const float*)d_in[9];

    int nm = in_sizes[2] / (Bq * Sq);   // router last-dim (4)

    static bool attr_done = false;
    if (!attr_done) {
        cudaFuncSetAttribute(fused_kernel,
                             cudaFuncAttributeMaxDynamicSharedMemorySize,
                             SMEM_FLOATS * 4);
        attr_done = true;
    }
    fused_kernel<<<BH, 512, SMEM_FLOATS * 4>>>(
        x, M, router, memid, Wk, bk, Wv, bv, Wf, bf, (float*)d_out, nm);
}

// round 9
// speedup vs baseline: 1.0907x; 1.0907x over previous
#include <cuda_runtime.h>
#include <math.h>

#define Bq 16
#define Sq 2048
#define Dq 128
#define Hq 8
#define BH 128
#define MCH 16                 // mem chunk (timesteps)
#define SCH 64                 // scan chunk
#define NCH (Sq/SCH)
#define CUT 1e-5f

// dynamic smem float layout
#define OFF_WK 0
#define OFF_WV 16384
#define OFF_X  32768           // 16 rows * stride 132 = 2112
#define OFF_K  34880           // 16 * 132 = 2112
#define OFF_V  36992           // 16 * 132 = 2112
#define OFF_C  39104           // 2048
#define SMEM_FLOATS 41152

typedef unsigned long long u64;

__device__ __forceinline__ u64 pack2(float lo, float hi) {
    u64 r; asm("mov.b64 %0, {%1, %2};" : "=l"(r) : "f"(lo), "f"(hi)); return r;
}
__device__ __forceinline__ void unpack2(u64 v, float& lo, float& hi) {
    asm("mov.b64 {%0, %1}, %2;" : "=f"(lo), "=f"(hi) : "l"(v));
}
__device__ __forceinline__ u64 fma2(u64 a, u64 b, u64 c) {
    u64 d; asm("fma.rn.f32x2 %0, %1, %2, %3;" : "=l"(d) : "l"(a), "l"(b), "l"(c));
    return d;
}

// ---------------------------------------------------------------------------
// One block per (b,h).
// Phase 0: cp.async prefetch of Wk_h/Wv_h into smem (completes after phase 1).
// Phase 1: backward scan w/ early exit; c_t = w_t*sp_t in smem; stop sp<CUT.
// Phase 2: chunked (16-step) K/V projection + rank-16 outer products, both in
//          packed f32x2 FFMA2; acc += P*M0 (skipped when P==0); store.
// ---------------------------------------------------------------------------
__global__ __launch_bounds__(512) void fused_kernel(
    const float* __restrict__ x, const float* __restrict__ M0,
    const float* __restrict__ router, const int* __restrict__ memid,
    const float* __restrict__ Wk, const float* __restrict__ bk,
    const float* __restrict__ Wv, const float* __restrict__ bv,
    const float* __restrict__ Wf, const float* __restrict__ bf,
    float* __restrict__ out, int nm)
{
    extern __shared__ float sm[];
    float* Wk_s = sm + OFF_WK;
    float* Wv_s = sm + OFF_WV;
    float* x_s  = sm + OFF_X;     // [row][d], stride 132
    float* k_s  = sm + OFF_K;     // [row][d], stride 132 (rows c-scaled)
    float* v_s  = sm + OFF_V;
    float* c_s  = sm + OFF_C;     // indexed by global t

    __shared__ float wfh[Dq];
    __shared__ float f_s[SCH], csp[SCH];
    __shared__ float s_sp, s_newsp;
    __shared__ int   s_t0i;

    int tid = threadIdx.x, bh = blockIdx.x, b = bh >> 3, h = bh & 7;

    // phase 0: async weight prefetch (overlaps with phase 1)
    for (int idx = tid; idx < Dq * 32; idx += 512) {
        int d = idx >> 5, q = idx & 31;
        unsigned int dk = (unsigned int)__cvta_generic_to_shared(&Wk_s[d * Dq + q * 4]);
        unsigned int dv = (unsigned int)__cvta_generic_to_shared(&Wv_s[d * Dq + q * 4]);
        const float* sk = &Wk[(size_t)d * (Dq * Hq) + h * Dq + q * 4];
        const float* sv = &Wv[(size_t)d * (Dq * Hq) + h * Dq + q * 4];
        asm volatile("cp.async.ca.shared.global [%0], [%1], 16;" :: "r"(dk), "l"(sk));
        asm volatile("cp.async.ca.shared.global [%0], [%1], 16;" :: "r"(dv), "l"(sv));
    }
    asm volatile("cp.async.commit_group;" ::: "memory");

    for (int d = tid; d < Dq; d += 512) wfh[d] = Wf[d * Hq + h];
    float bfh = bf[h];
    int mid = *memid;
    if (tid == 0) { s_sp = 1.0f; s_t0i = SCH; }
    __syncthreads();

    // ---- phase 1: backward scan with early exit ----
    int t0_exact = 0;
    float P = 0.0f;

    for (int ci = NCH - 1; ci >= 0; ci--) {
        int tc = ci * SCH;

        // f for 64 timesteps: 8 threads per t, direct LDG + shfl reduce
        {
            int t8 = tid >> 3, sub = tid & 7;
            const float* xp = &x[((size_t)b * Sq + tc + t8) * Dq + sub * 16];
            float a = 0.f;
            #pragma unroll
            for (int j = 0; j < 4; j++) {
                float4 xv = *(const float4*)&xp[j * 4];
                const float* wp = &wfh[sub * 16 + j * 4];
                a += xv.x * wp[0] + xv.y * wp[1] + xv.z * wp[2] + xv.w * wp[3];
            }
            a += __shfl_xor_sync(0xffffffffu, a, 1);
            a += __shfl_xor_sync(0xffffffffu, a, 2);
            a += __shfl_xor_sync(0xffffffffu, a, 4);
            if (sub == 0) f_s[t8] = 1.0f / (1.0f + __expf(-(a + bfh)));
        }
        __syncthreads();

        // warp 0: suffix-product scan over the 64 f values (2 per lane)
        if (tid < 32) {
            float f0 = f_s[2 * tid], f1 = f_s[2 * tid + 1];
            float p = f0 * f1;
            float incl = p;                       // prod_{j>=lane} p_j
            #pragma unroll
            for (int off = 1; off < 32; off <<= 1) {
                float v = __shfl_down_sync(0xffffffffu, incl, off);
                if (tid + off < 32) incl *= v;
            }
            float excl = __shfl_down_sync(0xffffffffu, incl, 1);
            if (tid == 31) excl = 1.0f;           // prod_{j>lane} p_j
            float sp0 = s_sp;
            float c1 = sp0 * excl;                // suffix after t = 2*lane+1
            float c0 = c1 * f1;                   // suffix after t = 2*lane
            csp[2 * tid]     = c0;
            csp[2 * tid + 1] = c1;
            if (tid == 0) s_newsp = sp0 * incl;
        }
        __syncthreads();

        if (tid < SCH) {
            float w = router[((size_t)b * Sq + tc + tid) * nm + mid];
            c_s[tc + tid] = w * csp[tid];
            if (csp[tid] >= CUT) atomicMin(&s_t0i, tid);
        }
        __syncthreads();

        float nsp = s_newsp;
        if (nsp < CUT) { t0_exact = tc + s_t0i; break; }   // uniform decision
        if (tid == 0) { s_sp = nsp; s_t0i = SCH; }
        if (ci == 0) { P = nsp; t0_exact = 0; }
        __syncthreads();
    }

    // weights must be resident before phase 2
    asm volatile("cp.async.wait_group 0;" ::: "memory");
    __syncthreads();

    // ---- phase 2: chunked projection + outer products (f32x2) ----
    int dg = tid >> 4, eg = tid & 15, d0 = dg * 4, e0 = eg * 8;
    u64 acc2[4][4];
    u64 z = pack2(0.f, 0.f);
    #pragma unroll
    for (int r = 0; r < 4; r++)
        #pragma unroll
        for (int q = 0; q < 4; q++) acc2[r][q] = z;

    int half = tid >> 8, id2 = tid & 255;
    int rg = id2 & 15;        // projection row (timestep within chunk)
    int cg = id2 >> 4;        // projection cols cg*8..+7
    float* op = half ? v_s : k_s;
    const float* Ws = half ? Wv_s : Wk_s;
    float bias[8];
    {
        const float* bsrc = half ? bv : bk;
        #pragma unroll
        for (int j = 0; j < 8; j++) bias[j] = bsrc[h * Dq + cg * 8 + j];
    }

    int t_start = t0_exact & ~(MCH - 1);
    for (int tc = t_start; tc < Sq; tc += MCH) {
        __syncthreads();
        // stage x chunk row-major: x_s[row][d], one warp per row
        {
            int row = tid >> 5, lane = tid & 31;
            float4 xv = *(const float4*)&x[((size_t)b * Sq + tc + row) * Dq + lane * 4];
            *(float4*)&x_s[row * 132 + lane * 4] = xv;
        }
        __syncthreads();

        // projection: 1 row x 8 cols as 4 packed f32x2 pairs
        u64 pa2[4] = {z, z, z, z};
        #pragma unroll 4
        for (int d4 = 0; d4 < Dq / 4; d4++) {
            float4 xa = *(const float4*)&x_s[rg * 132 + d4 * 4];
            float xr[4] = {xa.x, xa.y, xa.z, xa.w};
            #pragma unroll
            for (int u = 0; u < 4; u++) {
                int d = d4 * 4 + u;
                ulonglong2 wA = *(const ulonglong2*)&Ws[d * Dq + cg * 8];
                ulonglong2 wB = *(const ulonglong2*)&Ws[d * Dq + cg * 8 + 4];
                u64 xb = pack2(xr[u], xr[u]);
                pa2[0] = fma2(xb, wA.x, pa2[0]);
                pa2[1] = fma2(xb, wA.y, pa2[1]);
                pa2[2] = fma2(xb, wB.x, pa2[2]);
                pa2[3] = fma2(xb, wB.y, pa2[3]);
            }
        }
        {
            float scale = half ? 1.0f : c_s[tc + rg];   // fold c_t into k rows
            float o[8];
            #pragma unroll
            for (int q = 0; q < 4; q++) unpack2(pa2[q], o[2 * q], o[2 * q + 1]);
            #pragma unroll
            for (int j = 0; j < 8; j++) o[j] = (o[j] + bias[j]) * scale;
            *(float4*)&op[rg * 132 + cg * 8]     = make_float4(o[0], o[1], o[2], o[3]);
            *(float4*)&op[rg * 132 + cg * 8 + 4] = make_float4(o[4], o[5], o[6], o[7]);
        }
        __syncthreads();

        // rank-16 outer-product update: 4x8 tile as 4x4 packed pairs
        #pragma unroll 4
        for (int i = 0; i < MCH; i++) {
            float4 k0 = *(const float4*)&k_s[i * 132 + d0];
            ulonglong2 va = *(const ulonglong2*)&v_s[i * 132 + e0];
            ulonglong2 vb = *(const ulonglong2*)&v_s[i * 132 + e0 + 4];
            u64 kp[4] = {pack2(k0.x, k0.x), pack2(k0.y, k0.y),
                         pack2(k0.z, k0.z), pack2(k0.w, k0.w)};
            #pragma unroll
            for (int r = 0; r < 4; r++) {
                acc2[r][0] = fma2(kp[r], va.x, acc2[r][0]);
                acc2[r][1] = fma2(kp[r], va.y, acc2[r][1]);
                acc2[r][2] = fma2(kp[r], vb.x, acc2[r][2]);
                acc2[r][3] = fma2(kp[r], vb.y, acc2[r][3]);
            }
        }
    }

    // unpack accumulators
    float acc[4][8];
    #pragma unroll
    for (int r = 0; r < 4; r++)
        #pragma unroll
        for (int q = 0; q < 4; q++)
            unpack2(acc2[r][q], acc[r][2 * q], acc[r][2 * q + 1]);

    // add P*M0 only if the full scan completed (else contribution < CUT)
    if (P != 0.0f) {
        #pragma unroll
        for (int r = 0; r < 4; r++) {
            float4 m0 = *(const float4*)&M0[(((size_t)bh * Dq) + d0 + r) * Dq + e0];
            float4 m1 = *(const float4*)&M0[(((size_t)bh * Dq) + d0 + r) * Dq + e0 + 4];
            acc[r][0] += P * m0.x; acc[r][1] += P * m0.y;
            acc[r][2] += P * m0.z; acc[r][3] += P * m0.w;
            acc[r][4] += P * m1.x; acc[r][5] += P * m1.y;
            acc[r][6] += P * m1.z; acc[r][7] += P * m1.w;
        }
    }

    #pragma unroll
    for (int r = 0; r < 4; r++) {
        *(float4*)&out[(((size_t)bh * Dq) + d0 + r) * Dq + e0] =
            make_float4(acc[r][0], acc[r][1], acc[r][2], acc[r][3]);
        *(float4*)&out[(((size_t)bh * Dq) + d0 + r) * Dq + e0 + 4] =
            make_float4(acc[r][4], acc[r][5], acc[r][6], acc[r][7]);
    }
}

// ---------------------------------------------------------------------------
extern "C" void kernel_launch(void* const* d_in, const int* in_sizes, int n_in,
                              void* d_out, int out_size)
{
    const float* x      = (const float*)d_in[0];
    const float* M      = (const float*)d_in[1];
    const float* router = (const float*)d_in[2];
    const int*   memid  = (const int*)d_in[3];
    const float* Wk     = (const float*)d_in[4];
    const float* bk     = (const float*)d_in[5];
    const float* Wv     = (const float*)d_in[6];
    const float* bv     = (const float*)d_in[7];
    const float* Wf     = (const float*)d_in[8];
    const float* bf     = (const float*)d_in[9];

    int nm = in_sizes[2] / (Bq * Sq);   // router last-dim (4)

    static bool attr_done = false;
    if (!attr_done) {
        cudaFuncSetAttribute(fused_kernel,
                             cudaFuncAttributeMaxDynamicSharedMemorySize,
                             SMEM_FLOATS * 4);
        attr_done = true;
    }
    fused_kernel<<<BH, 512, SMEM_FLOATS * 4>>>(
        x, M, router, memid, Wk, bk, Wv, bv, Wf, bf, (float*)d_out, nm);
}